// round 10
// baseline (speedup 1.0000x reference)
#include <cuda_runtime.h>
#include <cuda_bf16.h>
#include <cstdint>

#define L_SEQ   16384
#define DIN     512
#define DH      1024
#define DOUT    512
#define T_CHUNK 64
#define N_CHUNK (L_SEQ / T_CHUNK)   // 256
#define K2      2560                 // concat K for GEMM2

// ---------------- scratch (device globals; runtime alloc forbidden) --------
__device__ __align__(128) float  g_bu_re[L_SEQ * DH];
__device__ __align__(128) float  g_bu_im[L_SEQ * DH];
__device__ __align__(128) float2 g_carry [N_CHUNK * DH];
__device__ __align__(128) float2 g_prefix[N_CHUNK * DH];

__device__ __align__(128) __nv_bfloat16 g_xh [L_SEQ * DIN];    // X hi
__device__ __align__(128) __nv_bfloat16 g_xl [L_SEQ * DIN];    // X lo
__device__ __align__(128) __nv_bfloat16 g_b1h[2 * DH * DIN];   // e^g*[Bre;Bim] hi
__device__ __align__(128) __nv_bfloat16 g_b1l[2 * DH * DIN];   // lo
__device__ __align__(128) __nv_bfloat16 g_hh [L_SEQ * 2 * DH]; // h=[re|im] hi
__device__ __align__(128) __nv_bfloat16 g_hl [L_SEQ * 2 * DH]; // lo
__device__ __align__(128) __nv_bfloat16 g_c2h[DOUT * K2];      // [Cre|-Cim|D] hi
__device__ __align__(128) __nv_bfloat16 g_c2l[DOUT * K2];      // lo

// ---------------- helpers --------------------------------------------------
__device__ __forceinline__ uint32_t smem_u32(const void* p) {
    uint32_t a;
    asm("{ .reg .u64 t; cvta.to.shared.u64 t, %1; cvt.u32.u64 %0, t; }"
        : "=r"(a) : "l"(p));
    return a;
}
__device__ __forceinline__ void cpa16(uint32_t dst, const void* src) {
    asm volatile("cp.async.cg.shared.global [%0], [%1], 16;"
                 :: "r"(dst), "l"(src) : "memory");
}
__device__ __forceinline__ void ldsm4(uint32_t& r0, uint32_t& r1, uint32_t& r2,
                                      uint32_t& r3, uint32_t a) {
    asm volatile("ldmatrix.sync.aligned.m8n8.x4.shared.b16 {%0,%1,%2,%3}, [%4];"
                 : "=r"(r0), "=r"(r1), "=r"(r2), "=r"(r3) : "r"(a));
}
__device__ __forceinline__ void mma16816(float& c0, float& c1, float& c2, float& c3,
                                         uint32_t a0, uint32_t a1, uint32_t a2,
                                         uint32_t a3, uint32_t b0, uint32_t b1) {
    asm volatile(
        "mma.sync.aligned.m16n8k16.row.col.f32.bf16.bf16.f32 "
        "{%0,%1,%2,%3}, {%4,%5,%6,%7}, {%8,%9}, {%0,%1,%2,%3};"
        : "+f"(c0), "+f"(c1), "+f"(c2), "+f"(c3)
        : "r"(a0), "r"(a1), "r"(a2), "r"(a3), "r"(b0), "r"(b1));
}

__device__ __forceinline__ float2 lambda_of(const float* __restrict__ lamb, int h) {
    float mag = expf(-expf(lamb[h]));
    float th  = expf(lamb[DH + h]);
    float s, c;
    sincosf(th, &s, &c);
    return make_float2(mag * c, mag * s);
}

__device__ __forceinline__ void split4(float4 v, __nv_bfloat16* ph, __nv_bfloat16* pl) {
    float f[4] = {v.x, v.y, v.z, v.w};
    #pragma unroll
    for (int i = 0; i < 4; i += 2) {
        __nv_bfloat16 h0 = __float2bfloat16(f[i]);
        __nv_bfloat16 h1 = __float2bfloat16(f[i + 1]);
        __nv_bfloat162 h2, l2;
        h2.x = h0; h2.y = h1;
        l2.x = __float2bfloat16(f[i] - __bfloat162float(h0));
        l2.y = __float2bfloat16(f[i + 1] - __bfloat162float(h1));
        *(__nv_bfloat162*)(ph + i) = h2;
        *(__nv_bfloat162*)(pl + i) = l2;
    }
}

struct alignas(8) bf4 { __nv_bfloat162 a, b; };

// ---------------- conversion kernels ---------------------------------------
__global__ void __launch_bounds__(256) k_cvt_x(const float* __restrict__ X) {
    int i = blockIdx.x * 256 + threadIdx.x;
    float4 v = ((const float4*)X)[i];
    split4(v, g_xh + 4 * (long)i, g_xl + 4 * (long)i);
}

__global__ void __launch_bounds__(256) k_cvt_b1(const float* __restrict__ Bre,
                                                const float* __restrict__ Bim,
                                                const float* __restrict__ gamma) {
    int i = blockIdx.x * 256 + threadIdx.x;
    int n  = i / (DIN / 4);
    int kq = (i % (DIN / 4)) * 4;
    float eg = expf(gamma[n & (DH - 1)]);
    const float* src = (n < DH) ? (Bre + (long)n * DIN) : (Bim + (long)(n - DH) * DIN);
    float4 v = *(const float4*)(src + kq);
    v.x *= eg; v.y *= eg; v.z *= eg; v.w *= eg;
    long o = (long)n * DIN + kq;
    split4(v, g_b1h + o, g_b1l + o);
}

__global__ void __launch_bounds__(256) k_cvt_c2(const float* __restrict__ Cre,
                                                const float* __restrict__ Cim,
                                                const float* __restrict__ Dm) {
    int i = blockIdx.x * 256 + threadIdx.x;
    int n  = i / (K2 / 4);
    int kq = (i % (K2 / 4)) * 4;
    float4 v;
    if (kq < 1024) {
        v = *(const float4*)(Cre + (long)n * DH + kq);
    } else if (kq < 2048) {
        v = *(const float4*)(Cim + (long)n * DH + (kq - 1024));
        v.x = -v.x; v.y = -v.y; v.z = -v.z; v.w = -v.w;
    } else {
        v = *(const float4*)(Dm + (long)n * DIN + (kq - 2048));
    }
    long o = (long)n * K2 + kq;
    split4(v, g_c2h + o, g_c2l + o);
}

// ---------------- mma.sync GEMM --------------------------------------------
// C[128x128 tile] = A @ B^T with A,B given as hi/lo bf16 planes.
// smem stage: Ah(8K) Al(8K) Bh(8K) Bl(8K) = 32KB, 3-stage (2 CTA/SM by regs).
// swizzle: byte = row*64 + ((chunk ^ ((row>>1)&3))*16), chunk = k16B index
#define ST_A_H 0
#define ST_A_L 8192
#define ST_B_H 16384
#define ST_B_L 24576
#define ST_SZ  32768
#define NSTAGE 3

template<int MODE>   // 0: GEMM1 (Bu), 1: GEMM2 (Y)
__global__ void __launch_bounds__(256, 2) k_mma(float* __restrict__ Y) {
    extern __shared__ char sm[];
    const int tid  = threadIdx.x;
    const int lane = tid & 31;
    const int wid  = tid >> 5;
    const int wm   = wid >> 2;          // 0..1 -> 64 rows each
    const int wn   = wid & 3;           // 0..3 -> 32 cols each
    const int m0   = blockIdx.y * 128;
    const int n0   = blockIdx.x * 128;
    const uint32_t smb = smem_u32(sm);
    const int NS = (MODE == 0) ? (DIN / 32) : (K2 / 32);

    float acc[4][4][4];
    #pragma unroll
    for (int a = 0; a < 4; a++)
        #pragma unroll
        for (int b = 0; b < 4; b++)
            #pragma unroll
            for (int c = 0; c < 4; c++) acc[a][b][c] = 0.f;

    // ldmatrix address components (x4: row = lane&15, k-half = lane>>4)
    const int rloc = lane & 15;
    const int khalf = lane >> 4;
    uint32_t aoff[4], asw[4];
    #pragma unroll
    for (int mf = 0; mf < 4; mf++) {
        int r = wm * 64 + mf * 16 + rloc;
        aoff[mf] = r * 64;
        asw[mf]  = (r >> 1) & 3;
    }
    uint32_t boff[2], bsw[2];
    #pragma unroll
    for (int np = 0; np < 2; np++) {
        int r = wn * 32 + np * 16 + rloc;
        boff[np] = r * 64;
        bsw[np]  = (r >> 1) & 3;
    }

    auto issue_stage = [&](int s, int buf) {
        uint32_t base = smb + buf * ST_SZ;
        int k0 = s * 32;
        const __nv_bfloat16 *Ah, *Al, *Bh, *Bl;
        long lda, ldb; int ka, kb;
        if (MODE == 0) {
            Ah = g_xh; Al = g_xl; lda = DIN; ka = k0;
            Bh = g_b1h; Bl = g_b1l; ldb = DIN; kb = k0;
        } else {
            if (k0 < 2 * DH) { Ah = g_hh; Al = g_hl; lda = 2 * DH; ka = k0; }
            else             { Ah = g_xh; Al = g_xl; lda = DIN;    ka = k0 - 2 * DH; }
            Bh = g_c2h; Bl = g_c2l; ldb = K2; kb = k0;
        }
        #pragma unroll
        for (int t = 0; t < 2; t++) {
            int idx = tid + t * 256;
            int row = idx >> 2, ch = idx & 3;
            uint32_t doff = row * 64 + ((ch ^ ((row >> 1) & 3)) * 16);
            long ao = (long)(m0 + row) * lda + ka + ch * 8;
            long bo = (long)(n0 + row) * ldb + kb + ch * 8;
            cpa16(base + ST_A_H + doff, Ah + ao);
            cpa16(base + ST_A_L + doff, Al + ao);
            cpa16(base + ST_B_H + doff, Bh + bo);
            cpa16(base + ST_B_L + doff, Bl + bo);
        }
        asm volatile("cp.async.commit_group;" ::: "memory");
    };

    issue_stage(0, 0);
    issue_stage(1, 1);

    int cb = 0;   // compute buffer for stage s
    for (int s = 0; s < NS; s++) {
        if (s + 2 < NS) {
            int ib = cb + 2; if (ib >= NSTAGE) ib -= NSTAGE;
            issue_stage(s + 2, ib);
            asm volatile("cp.async.wait_group 2;" ::: "memory");
        } else if (s + 1 < NS) {
            asm volatile("cp.async.wait_group 1;" ::: "memory");
        } else {
            asm volatile("cp.async.wait_group 0;" ::: "memory");
        }
        __syncthreads();

        uint32_t base = smb + cb * ST_SZ;
        #pragma unroll
        for (int ks = 0; ks < 2; ks++) {
            const int chunk = ks * 2 + khalf;
            uint32_t ra[4][4], rbh[2][4], rbl[2][4];

            // load A hi + B hi
            #pragma unroll
            for (int mf = 0; mf < 4; mf++)
                ldsm4(ra[mf][0], ra[mf][1], ra[mf][2], ra[mf][3],
                      base + ST_A_H + aoff[mf] + ((chunk ^ asw[mf]) * 16));
            #pragma unroll
            for (int np = 0; np < 2; np++)
                ldsm4(rbh[np][0], rbh[np][1], rbh[np][2], rbh[np][3],
                      base + ST_B_H + boff[np] + ((chunk ^ bsw[np]) * 16));
            // pass 1: Ah * Bh
            #pragma unroll
            for (int mf = 0; mf < 4; mf++)
                #pragma unroll
                for (int nf = 0; nf < 4; nf++) {
                    int np = nf >> 1, sel = nf & 1;
                    mma16816(acc[mf][nf][0], acc[mf][nf][1], acc[mf][nf][2], acc[mf][nf][3],
                             ra[mf][0], ra[mf][1], ra[mf][2], ra[mf][3],
                             rbh[np][sel], rbh[np][sel + 2]);
                }
            // load B lo; pass 2: Ah * Bl (reuse ra)
            #pragma unroll
            for (int np = 0; np < 2; np++)
                ldsm4(rbl[np][0], rbl[np][1], rbl[np][2], rbl[np][3],
                      base + ST_B_L + boff[np] + ((chunk ^ bsw[np]) * 16));
            #pragma unroll
            for (int mf = 0; mf < 4; mf++)
                #pragma unroll
                for (int nf = 0; nf < 4; nf++) {
                    int np = nf >> 1, sel = nf & 1;
                    mma16816(acc[mf][nf][0], acc[mf][nf][1], acc[mf][nf][2], acc[mf][nf][3],
                             ra[mf][0], ra[mf][1], ra[mf][2], ra[mf][3],
                             rbl[np][sel], rbl[np][sel + 2]);
                }
            // load A lo (overwrite ra); pass 3: Al * Bh (reuse rbh)
            #pragma unroll
            for (int mf = 0; mf < 4; mf++)
                ldsm4(ra[mf][0], ra[mf][1], ra[mf][2], ra[mf][3],
                      base + ST_A_L + aoff[mf] + ((chunk ^ asw[mf]) * 16));
            #pragma unroll
            for (int mf = 0; mf < 4; mf++)
                #pragma unroll
                for (int nf = 0; nf < 4; nf++) {
                    int np = nf >> 1, sel = nf & 1;
                    mma16816(acc[mf][nf][0], acc[mf][nf][1], acc[mf][nf][2], acc[mf][nf][3],
                             ra[mf][0], ra[mf][1], ra[mf][2], ra[mf][3],
                             rbh[np][sel], rbh[np][sel + 2]);
                }
        }
        __syncthreads();
        cb = (cb + 1 == NSTAGE) ? 0 : cb + 1;
    }

    // epilogue
    if (MODE == 0) {
        float* plane = (n0 < DH) ? g_bu_re : g_bu_im;
        int nbase = n0 & (DH - 1);
        #pragma unroll
        for (int mf = 0; mf < 4; mf++) {
            int m = m0 + wm * 64 + mf * 16 + (lane >> 2);
            #pragma unroll
            for (int nf = 0; nf < 4; nf++) {
                int nn = nbase + wn * 32 + nf * 8 + (lane & 3) * 2;
                *(float2*)(plane + (long)m * DH + nn) =
                    make_float2(acc[mf][nf][0], acc[mf][nf][1]);
                *(float2*)(plane + (long)(m + 8) * DH + nn) =
                    make_float2(acc[mf][nf][2], acc[mf][nf][3]);
            }
        }
    } else {
        #pragma unroll
        for (int mf = 0; mf < 4; mf++) {
            int m = m0 + wm * 64 + mf * 16 + (lane >> 2);
            #pragma unroll
            for (int nf = 0; nf < 4; nf++) {
                int nn = n0 + wn * 32 + nf * 8 + (lane & 3) * 2;
                *(float2*)(Y + (long)m * DOUT + nn) =
                    make_float2(acc[mf][nf][0], acc[mf][nf][1]);
                *(float2*)(Y + (long)(m + 8) * DOUT + nn) =
                    make_float2(acc[mf][nf][2], acc[mf][nf][3]);
            }
        }
    }
}

// ---------------- scan phase A: chunk carries, 4 channels/thread -----------
__global__ void __launch_bounds__(256) k_carry(const float* __restrict__ lamb) {
    const int h0 = (blockIdx.x * 256 + threadIdx.x) * 4;
    const int c  = blockIdx.y;
    float2 lam[4];
    #pragma unroll
    for (int j = 0; j < 4; j++) lam[j] = lambda_of(lamb, h0 + j);

    float hr[4] = {0.f, 0.f, 0.f, 0.f}, hi[4] = {0.f, 0.f, 0.f, 0.f};
    long base = (long)c * T_CHUNK * DH + h0;
    #pragma unroll 4
    for (int t = 0; t < T_CHUNK; t++) {
        long idx = base + (long)t * DH;
        float4 ur = *(const float4*)(g_bu_re + idx);
        float4 ui = *(const float4*)(g_bu_im + idx);
        float u_r[4] = {ur.x, ur.y, ur.z, ur.w};
        float u_i[4] = {ui.x, ui.y, ui.z, ui.w};
        #pragma unroll
        for (int j = 0; j < 4; j++) {
            float nr = fmaf(lam[j].x, hr[j], fmaf(-lam[j].y, hi[j], u_r[j]));
            float ni = fmaf(lam[j].x, hi[j], fmaf( lam[j].y, hr[j], u_i[j]));
            hr[j] = nr; hi[j] = ni;
        }
    }
    #pragma unroll
    for (int j = 0; j < 4; j++)
        g_carry[c * DH + h0 + j] = make_float2(hr[j], hi[j]);
}

// ---------------- scan phase B ---------------------------------------------
__global__ void __launch_bounds__(256) k_scan_chunks(const float* __restrict__ lamb) {
    const int h = blockIdx.x * 256 + threadIdx.x;
    float2 lam = lambda_of(lamb, h);
    float2 lt = lam;
    #pragma unroll
    for (int i = 0; i < 6; i++) {
        float nr = lt.x * lt.x - lt.y * lt.y;
        float ni = 2.f * lt.x * lt.y;
        lt.x = nr; lt.y = ni;
    }
    float pr = 0.f, pi = 0.f;
    #pragma unroll 4
    for (int c = 0; c < N_CHUNK; c++) {
        g_prefix[c * DH + h] = make_float2(pr, pi);
        float2 e = g_carry[c * DH + h];
        float nr = fmaf(lt.x, pr, fmaf(-lt.y, pi, e.x));
        float ni = fmaf(lt.x, pi, fmaf( lt.y, pr, e.y));
        pr = nr; pi = ni;
    }
}

// ---------------- scan phase C: apply + emit bf16 hi/lo, 4 ch/thread -------
__global__ void __launch_bounds__(256) k_apply(const float* __restrict__ lamb) {
    const int h0 = (blockIdx.x * 256 + threadIdx.x) * 4;
    const int c  = blockIdx.y;
    float2 lam[4];
    #pragma unroll
    for (int j = 0; j < 4; j++) lam[j] = lambda_of(lamb, h0 + j);

    float hr[4], hi[4];
    #pragma unroll
    for (int j = 0; j < 4; j++) {
        float2 P = g_prefix[c * DH + h0 + j];
        hr[j] = P.x; hi[j] = P.y;
    }

    long base = (long)c * T_CHUNK * DH + h0;
    #pragma unroll 4
    for (int t = 0; t < T_CHUNK; t++) {
        long idx = base + (long)t * DH;
        float4 ur = *(const float4*)(g_bu_re + idx);
        float4 ui = *(const float4*)(g_bu_im + idx);
        float u_r[4] = {ur.x, ur.y, ur.z, ur.w};
        float u_i[4] = {ui.x, ui.y, ui.z, ui.w};
        #pragma unroll
        for (int j = 0; j < 4; j++) {
            float nr = fmaf(lam[j].x, hr[j], fmaf(-lam[j].y, hi[j], u_r[j]));
            float ni = fmaf(lam[j].x, hi[j], fmaf( lam[j].y, hr[j], u_i[j]));
            hr[j] = nr; hi[j] = ni;
        }

        long m  = (long)c * T_CHUNK + t;
        long ob = m * (2 * DH) + h0;
        bf4 o;
        // re hi
        o.a.x = __float2bfloat16(hr[0]); o.a.y = __float2bfloat16(hr[1]);
        o.b.x = __float2bfloat16(hr[2]); o.b.y = __float2bfloat16(hr[3]);
        *(bf4*)(g_hh + ob) = o;
        // re lo
        bf4 ol;
        ol.a.x = __float2bfloat16(hr[0] - __bfloat162float(o.a.x));
        ol.a.y = __float2bfloat16(hr[1] - __bfloat162float(o.a.y));
        ol.b.x = __float2bfloat16(hr[2] - __bfloat162float(o.b.x));
        ol.b.y = __float2bfloat16(hr[3] - __bfloat162float(o.b.y));
        *(bf4*)(g_hl + ob) = ol;
        // im hi
        o.a.x = __float2bfloat16(hi[0]); o.a.y = __float2bfloat16(hi[1]);
        o.b.x = __float2bfloat16(hi[2]); o.b.y = __float2bfloat16(hi[3]);
        *(bf4*)(g_hh + ob + DH) = o;
        // im lo
        ol.a.x = __float2bfloat16(hi[0] - __bfloat162float(o.a.x));
        ol.a.y = __float2bfloat16(hi[1] - __bfloat162float(o.a.y));
        ol.b.x = __float2bfloat16(hi[2] - __bfloat162float(o.b.x));
        ol.b.y = __float2bfloat16(hi[3] - __bfloat162float(o.b.y));
        *(bf4*)(g_hl + ob + DH) = ol;
    }
}

// ---------------------------------------------------------------------------
extern "C" void kernel_launch(void* const* d_in, const int* in_sizes, int n_in,
                              void* d_out, int out_size)
{
    const float* X     = (const float*)d_in[0];
    const float* lamb  = (const float*)d_in[1];
    const float* gamma = (const float*)d_in[2];
    const float* Bre   = (const float*)d_in[3];
    const float* Bim   = (const float*)d_in[4];
    const float* Cre   = (const float*)d_in[5];
    const float* Cim   = (const float*)d_in[6];
    const float* Dm    = (const float*)d_in[7];
    float*       Y     = (float*)d_out;

    const int SMEM = NSTAGE * ST_SZ;   // 96 KB
    cudaFuncSetAttribute(k_mma<0>, cudaFuncAttributeMaxDynamicSharedMemorySize, SMEM);
    cudaFuncSetAttribute(k_mma<1>, cudaFuncAttributeMaxDynamicSharedMemorySize, SMEM);

    k_cvt_x <<<(L_SEQ * DIN / 4) / 256, 256>>>(X);
    k_cvt_b1<<<(2 * DH * DIN / 4) / 256, 256>>>(Bre, Bim, gamma);
    k_cvt_c2<<<(DOUT * K2 / 4) / 256, 256>>>(Cre, Cim, Dm);

    k_mma<0><<<dim3(2 * DH / 128, L_SEQ / 128), 256, SMEM>>>(nullptr);

    k_carry      <<<dim3(1, N_CHUNK), 256>>>(lamb);
    k_scan_chunks<<<DH / 256, 256>>>(lamb);
    k_apply      <<<dim3(1, N_CHUNK), 256>>>(lamb);

    k_mma<1><<<dim3(DOUT / 128, L_SEQ / 128), 256, SMEM>>>(Y);
}

// round 12
// speedup vs baseline: 1.0103x; 1.0103x over previous
#include <cuda_runtime.h>
#include <cuda_bf16.h>
#include <cstdint>

#define L_SEQ   16384
#define DIN     512
#define DH      1024
#define DOUT    512
#define T_CHUNK 64
#define N_CHUNK (L_SEQ / T_CHUNK)   // 256
#define K2      2560                 // concat K for GEMM2

// ---------------- scratch (device globals; runtime alloc forbidden) --------
__device__ __align__(128) float  g_bu_re[L_SEQ * DH];
__device__ __align__(128) float  g_bu_im[L_SEQ * DH];
__device__ __align__(128) float2 g_carry [N_CHUNK * DH];
__device__ __align__(128) float2 g_prefix[N_CHUNK * DH];

__device__ __align__(128) __nv_bfloat16 g_xh [L_SEQ * DIN];    // X hi
__device__ __align__(128) __nv_bfloat16 g_xl [L_SEQ * DIN];    // X lo
__device__ __align__(128) __nv_bfloat16 g_b1h[2 * DH * DIN];   // e^g*[Bre;Bim] hi
__device__ __align__(128) __nv_bfloat16 g_b1l[2 * DH * DIN];   // lo
__device__ __align__(128) __nv_bfloat16 g_hh [L_SEQ * 2 * DH]; // h=[re|im] hi
__device__ __align__(128) __nv_bfloat16 g_hl [L_SEQ * 2 * DH]; // lo
__device__ __align__(128) __nv_bfloat16 g_c2h[DOUT * K2];      // [Cre|-Cim|D] hi
__device__ __align__(128) __nv_bfloat16 g_c2l[DOUT * K2];      // lo

// ---------------- helpers --------------------------------------------------
__device__ __forceinline__ uint32_t smem_u32(const void* p) {
    uint32_t a;
    asm("{ .reg .u64 t; cvta.to.shared.u64 t, %1; cvt.u32.u64 %0, t; }"
        : "=r"(a) : "l"(p));
    return a;
}
__device__ __forceinline__ void cpa16(uint32_t dst, const void* src) {
    asm volatile("cp.async.cg.shared.global [%0], [%1], 16;"
                 :: "r"(dst), "l"(src) : "memory");
}
__device__ __forceinline__ void ldsm4(uint32_t& r0, uint32_t& r1, uint32_t& r2,
                                      uint32_t& r3, uint32_t a) {
    asm volatile("ldmatrix.sync.aligned.m8n8.x4.shared.b16 {%0,%1,%2,%3}, [%4];"
                 : "=r"(r0), "=r"(r1), "=r"(r2), "=r"(r3) : "r"(a));
}
__device__ __forceinline__ void mma16816(float& c0, float& c1, float& c2, float& c3,
                                         uint32_t a0, uint32_t a1, uint32_t a2,
                                         uint32_t a3, uint32_t b0, uint32_t b1) {
    asm volatile(
        "mma.sync.aligned.m16n8k16.row.col.f32.bf16.bf16.f32 "
        "{%0,%1,%2,%3}, {%4,%5,%6,%7}, {%8,%9}, {%0,%1,%2,%3};"
        : "+f"(c0), "+f"(c1), "+f"(c2), "+f"(c3)
        : "r"(a0), "r"(a1), "r"(a2), "r"(a3), "r"(b0), "r"(b1));
}

__device__ __forceinline__ float2 lambda_of(const float* __restrict__ lamb, int h) {
    float mag = expf(-expf(lamb[h]));
    float th  = expf(lamb[DH + h]);
    float s, c;
    sincosf(th, &s, &c);
    return make_float2(mag * c, mag * s);
}

__device__ __forceinline__ void split4(float4 v, __nv_bfloat16* ph, __nv_bfloat16* pl) {
    float f[4] = {v.x, v.y, v.z, v.w};
    #pragma unroll
    for (int i = 0; i < 4; i += 2) {
        __nv_bfloat16 h0 = __float2bfloat16(f[i]);
        __nv_bfloat16 h1 = __float2bfloat16(f[i + 1]);
        __nv_bfloat162 h2, l2;
        h2.x = h0; h2.y = h1;
        l2.x = __float2bfloat16(f[i] - __bfloat162float(h0));
        l2.y = __float2bfloat16(f[i + 1] - __bfloat162float(h1));
        *(__nv_bfloat162*)(ph + i) = h2;
        *(__nv_bfloat162*)(pl + i) = l2;
    }
}

// ---------------- conversion kernels ---------------------------------------
__global__ void __launch_bounds__(256) k_cvt_x(const float* __restrict__ X) {
    int i = blockIdx.x * 256 + threadIdx.x;
    float4 v = ((const float4*)X)[i];
    split4(v, g_xh + 4 * (long)i, g_xl + 4 * (long)i);
}

__global__ void __launch_bounds__(256) k_cvt_b1(const float* __restrict__ Bre,
                                                const float* __restrict__ Bim,
                                                const float* __restrict__ gamma) {
    int i = blockIdx.x * 256 + threadIdx.x;
    int n  = i / (DIN / 4);
    int kq = (i % (DIN / 4)) * 4;
    float eg = expf(gamma[n & (DH - 1)]);
    const float* src = (n < DH) ? (Bre + (long)n * DIN) : (Bim + (long)(n - DH) * DIN);
    float4 v = *(const float4*)(src + kq);
    v.x *= eg; v.y *= eg; v.z *= eg; v.w *= eg;
    long o = (long)n * DIN + kq;
    split4(v, g_b1h + o, g_b1l + o);
}

__global__ void __launch_bounds__(256) k_cvt_c2(const float* __restrict__ Cre,
                                                const float* __restrict__ Cim,
                                                const float* __restrict__ Dm) {
    int i = blockIdx.x * 256 + threadIdx.x;
    int n  = i / (K2 / 4);
    int kq = (i % (K2 / 4)) * 4;
    float4 v;
    if (kq < 1024) {
        v = *(const float4*)(Cre + (long)n * DH + kq);
    } else if (kq < 2048) {
        v = *(const float4*)(Cim + (long)n * DH + (kq - 1024));
        v.x = -v.x; v.y = -v.y; v.z = -v.z; v.w = -v.w;
    } else {
        v = *(const float4*)(Dm + (long)n * DIN + (kq - 2048));
    }
    long o = (long)n * K2 + kq;
    split4(v, g_c2h + o, g_c2l + o);
}

// ============================================================================
// GEMM1: Bu = X @ B'^T. CTA tile 128(M) x 64(N), warp tile 64x16,
// 2-stage cp.async, 3 CTA/SM (regs <= 85). smem/stage = 24KB.
// ============================================================================
#define S1_A_H 0
#define S1_A_L 8192
#define S1_B_H 16384
#define S1_B_L 20480
#define S1_SZ  24576

__global__ void __launch_bounds__(256, 3) k_gemm1() {
    extern __shared__ char sm[];
    const int tid  = threadIdx.x;
    const int lane = tid & 31;
    const int wid  = tid >> 5;
    const int wm   = wid >> 2;          // 0..1 -> 64 rows
    const int wn   = wid & 3;           // 0..3 -> 16 cols
    const int m0   = blockIdx.y * 128;
    const int n0   = blockIdx.x * 64;
    const uint32_t smb = smem_u32(sm);
    const int NS = DIN / 32;

    float acc[4][2][4];
    #pragma unroll
    for (int a = 0; a < 4; a++)
        #pragma unroll
        for (int b = 0; b < 2; b++)
            #pragma unroll
            for (int c = 0; c < 4; c++) acc[a][b][c] = 0.f;

    const int rloc = lane & 15;
    const int khalf = lane >> 4;
    uint32_t aoff[4], asw[4];
    #pragma unroll
    for (int mf = 0; mf < 4; mf++) {
        int r = wm * 64 + mf * 16 + rloc;
        aoff[mf] = r * 64;
        asw[mf]  = (r >> 1) & 3;
    }
    uint32_t boff, bsw;
    {
        int r = wn * 16 + rloc;
        boff = r * 64;
        bsw  = (r >> 1) & 3;
    }

    auto issue_stage = [&](int s, int buf) {
        uint32_t base = smb + buf * S1_SZ;
        int k0 = s * 32;
        // A: 128 rows x 4 chunks = 512 granules (2/thread/plane)
        #pragma unroll
        for (int t = 0; t < 2; t++) {
            int idx = tid + t * 256;
            int row = idx >> 2, ch = idx & 3;
            uint32_t doff = row * 64 + ((ch ^ ((row >> 1) & 3)) * 16);
            long ao = (long)(m0 + row) * DIN + k0 + ch * 8;
            cpa16(base + S1_A_H + doff, g_xh + ao);
            cpa16(base + S1_A_L + doff, g_xl + ao);
        }
        // B: 64 rows x 4 chunks = 256 granules (1/thread/plane)
        {
            int row = tid >> 2, ch = tid & 3;
            uint32_t doff = row * 64 + ((ch ^ ((row >> 1) & 3)) * 16);
            long bo = (long)(n0 + row) * DIN + k0 + ch * 8;
            cpa16(base + S1_B_H + doff, g_b1h + bo);
            cpa16(base + S1_B_L + doff, g_b1l + bo);
        }
        asm volatile("cp.async.commit_group;" ::: "memory");
    };

    issue_stage(0, 0);

    for (int s = 0; s < NS; s++) {
        if (s + 1 < NS) {
            issue_stage(s + 1, (s + 1) & 1);
            asm volatile("cp.async.wait_group 1;" ::: "memory");
        } else {
            asm volatile("cp.async.wait_group 0;" ::: "memory");
        }
        __syncthreads();

        uint32_t base = smb + (s & 1) * S1_SZ;
        #pragma unroll
        for (int ks = 0; ks < 2; ks++) {
            const int chunk = ks * 2 + khalf;
            uint32_t ra[4][4], rbh[4], rbl[4];

            #pragma unroll
            for (int mf = 0; mf < 4; mf++)
                ldsm4(ra[mf][0], ra[mf][1], ra[mf][2], ra[mf][3],
                      base + S1_A_H + aoff[mf] + ((chunk ^ asw[mf]) * 16));
            ldsm4(rbh[0], rbh[1], rbh[2], rbh[3],
                  base + S1_B_H + boff + ((chunk ^ bsw) * 16));
            // pass 1: Ah * Bh
            #pragma unroll
            for (int mf = 0; mf < 4; mf++)
                #pragma unroll
                for (int nf = 0; nf < 2; nf++)
                    mma16816(acc[mf][nf][0], acc[mf][nf][1], acc[mf][nf][2], acc[mf][nf][3],
                             ra[mf][0], ra[mf][1], ra[mf][2], ra[mf][3],
                             rbh[nf], rbh[nf + 2]);
            // pass 2: Ah * Bl
            ldsm4(rbl[0], rbl[1], rbl[2], rbl[3],
                  base + S1_B_L + boff + ((chunk ^ bsw) * 16));
            #pragma unroll
            for (int mf = 0; mf < 4; mf++)
                #pragma unroll
                for (int nf = 0; nf < 2; nf++)
                    mma16816(acc[mf][nf][0], acc[mf][nf][1], acc[mf][nf][2], acc[mf][nf][3],
                             ra[mf][0], ra[mf][1], ra[mf][2], ra[mf][3],
                             rbl[nf], rbl[nf + 2]);
            // pass 3: Al * Bh (overwrite ra)
            #pragma unroll
            for (int mf = 0; mf < 4; mf++)
                ldsm4(ra[mf][0], ra[mf][1], ra[mf][2], ra[mf][3],
                      base + S1_A_L + aoff[mf] + ((chunk ^ asw[mf]) * 16));
            #pragma unroll
            for (int mf = 0; mf < 4; mf++)
                #pragma unroll
                for (int nf = 0; nf < 2; nf++)
                    mma16816(acc[mf][nf][0], acc[mf][nf][1], acc[mf][nf][2], acc[mf][nf][3],
                             ra[mf][0], ra[mf][1], ra[mf][2], ra[mf][3],
                             rbh[nf], rbh[nf + 2]);
        }
        __syncthreads();
    }

    float* plane = (n0 < DH) ? g_bu_re : g_bu_im;
    int nbase = n0 & (DH - 1);
    #pragma unroll
    for (int mf = 0; mf < 4; mf++) {
        int m = m0 + wm * 64 + mf * 16 + (lane >> 2);
        #pragma unroll
        for (int nf = 0; nf < 2; nf++) {
            int nn = nbase + wn * 16 + nf * 8 + (lane & 3) * 2;
            *(float2*)(plane + (long)m * DH + nn) =
                make_float2(acc[mf][nf][0], acc[mf][nf][1]);
            *(float2*)(plane + (long)(m + 8) * DH + nn) =
                make_float2(acc[mf][nf][2], acc[mf][nf][3]);
        }
    }
}

// ============================================================================
// GEMM2: Y = [h_re|h_im|X] @ [Cre|-Cim|D]^T. R8 config: 128x128 tile,
// warp 64x32, 2-stage, 2 CTA/SM.
// ============================================================================
#define ST_A_H 0
#define ST_A_L 8192
#define ST_B_H 16384
#define ST_B_L 24576
#define ST_SZ  32768

__global__ void __launch_bounds__(256, 2) k_gemm2(float* __restrict__ Y) {
    extern __shared__ char sm[];
    const int tid  = threadIdx.x;
    const int lane = tid & 31;
    const int wid  = tid >> 5;
    const int wm   = wid >> 2;
    const int wn   = wid & 3;
    const int m0   = blockIdx.y * 128;
    const int n0   = blockIdx.x * 128;
    const uint32_t smb = smem_u32(sm);
    const int NS = K2 / 32;

    float acc[4][4][4];
    #pragma unroll
    for (int a = 0; a < 4; a++)
        #pragma unroll
        for (int b = 0; b < 4; b++)
            #pragma unroll
            for (int c = 0; c < 4; c++) acc[a][b][c] = 0.f;

    const int rloc = lane & 15;
    const int khalf = lane >> 4;
    uint32_t aoff[4], asw[4];
    #pragma unroll
    for (int mf = 0; mf < 4; mf++) {
        int r = wm * 64 + mf * 16 + rloc;
        aoff[mf] = r * 64;
        asw[mf]  = (r >> 1) & 3;
    }
    uint32_t boff[2], bsw[2];
    #pragma unroll
    for (int np = 0; np < 2; np++) {
        int r = wn * 32 + np * 16 + rloc;
        boff[np] = r * 64;
        bsw[np]  = (r >> 1) & 3;
    }

    auto issue_stage = [&](int s, int buf) {
        uint32_t base = smb + buf * ST_SZ;
        int k0 = s * 32;
        const __nv_bfloat16 *Ah, *Al;
        long lda; int ka;
        if (k0 < 2 * DH) { Ah = g_hh; Al = g_hl; lda = 2 * DH; ka = k0; }
        else             { Ah = g_xh; Al = g_xl; lda = DIN;    ka = k0 - 2 * DH; }
        #pragma unroll
        for (int t = 0; t < 2; t++) {
            int idx = tid + t * 256;
            int row = idx >> 2, ch = idx & 3;
            uint32_t doff = row * 64 + ((ch ^ ((row >> 1) & 3)) * 16);
            long ao = (long)(m0 + row) * lda + ka + ch * 8;
            long bo = (long)(n0 + row) * K2 + k0 + ch * 8;
            cpa16(base + ST_A_H + doff, Ah + ao);
            cpa16(base + ST_A_L + doff, Al + ao);
            cpa16(base + ST_B_H + doff, g_c2h + bo);
            cpa16(base + ST_B_L + doff, g_c2l + bo);
        }
        asm volatile("cp.async.commit_group;" ::: "memory");
    };

    issue_stage(0, 0);

    for (int s = 0; s < NS; s++) {
        if (s + 1 < NS) {
            issue_stage(s + 1, (s + 1) & 1);
            asm volatile("cp.async.wait_group 1;" ::: "memory");
        } else {
            asm volatile("cp.async.wait_group 0;" ::: "memory");
        }
        __syncthreads();

        uint32_t base = smb + (s & 1) * ST_SZ;
        #pragma unroll
        for (int ks = 0; ks < 2; ks++) {
            const int chunk = ks * 2 + khalf;
            uint32_t ra[4][4], rbh[2][4], rbl[2][4];

            #pragma unroll
            for (int mf = 0; mf < 4; mf++)
                ldsm4(ra[mf][0], ra[mf][1], ra[mf][2], ra[mf][3],
                      base + ST_A_H + aoff[mf] + ((chunk ^ asw[mf]) * 16));
            #pragma unroll
            for (int np = 0; np < 2; np++)
                ldsm4(rbh[np][0], rbh[np][1], rbh[np][2], rbh[np][3],
                      base + ST_B_H + boff[np] + ((chunk ^ bsw[np]) * 16));
            #pragma unroll
            for (int mf = 0; mf < 4; mf++)
                #pragma unroll
                for (int nf = 0; nf < 4; nf++) {
                    int np = nf >> 1, sel = nf & 1;
                    mma16816(acc[mf][nf][0], acc[mf][nf][1], acc[mf][nf][2], acc[mf][nf][3],
                             ra[mf][0], ra[mf][1], ra[mf][2], ra[mf][3],
                             rbh[np][sel], rbh[np][sel + 2]);
                }
            #pragma unroll
            for (int np = 0; np < 2; np++)
                ldsm4(rbl[np][0], rbl[np][1], rbl[np][2], rbl[np][3],
                      base + ST_B_L + boff[np] + ((chunk ^ bsw[np]) * 16));
            #pragma unroll
            for (int mf = 0; mf < 4; mf++)
                #pragma unroll
                for (int nf = 0; nf < 4; nf++) {
                    int np = nf >> 1, sel = nf & 1;
                    mma16816(acc[mf][nf][0], acc[mf][nf][1], acc[mf][nf][2], acc[mf][nf][3],
                             ra[mf][0], ra[mf][1], ra[mf][2], ra[mf][3],
                             rbl[np][sel], rbl[np][sel + 2]);
                }
            #pragma unroll
            for (int mf = 0; mf < 4; mf++)
                ldsm4(ra[mf][0], ra[mf][1], ra[mf][2], ra[mf][3],
                      base + ST_A_L + aoff[mf] + ((chunk ^ asw[mf]) * 16));
            #pragma unroll
            for (int mf = 0; mf < 4; mf++)
                #pragma unroll
                for (int nf = 0; nf < 4; nf++) {
                    int np = nf >> 1, sel = nf & 1;
                    mma16816(acc[mf][nf][0], acc[mf][nf][1], acc[mf][nf][2], acc[mf][nf][3],
                             ra[mf][0], ra[mf][1], ra[mf][2], ra[mf][3],
                             rbh[np][sel], rbh[np][sel + 2]);
                }
        }
        __syncthreads();
    }

    #pragma unroll
    for (int mf = 0; mf < 4; mf++) {
        int m = m0 + wm * 64 + mf * 16 + (lane >> 2);
        #pragma unroll
        for (int nf = 0; nf < 4; nf++) {
            int nn = n0 + wn * 32 + nf * 8 + (lane & 3) * 2;
            *(float2*)(Y + (long)m * DOUT + nn) =
                make_float2(acc[mf][nf][0], acc[mf][nf][1]);
            *(float2*)(Y + (long)(m + 8) * DOUT + nn) =
                make_float2(acc[mf][nf][2], acc[mf][nf][3]);
        }
    }
}

// ---------------- scan phase A: chunk carries (R8: 2 ch/thread) ------------
__global__ void __launch_bounds__(256) k_carry(const float* __restrict__ lamb) {
    const int hp = blockIdx.x * 256 + threadIdx.x;
    const int c  = blockIdx.y;
    const int h0 = hp * 2;
    const float2 lA = lambda_of(lamb, h0);
    const float2 lB = lambda_of(lamb, h0 + 1);

    float ar = 0.f, ai = 0.f, br = 0.f, bi = 0.f;
    long base = (long)c * T_CHUNK * DH + h0;
    #pragma unroll 4
    for (int t = 0; t < T_CHUNK; t++) {
        long idx = base + (long)t * DH;
        float2 ur = *(const float2*)(g_bu_re + idx);
        float2 ui = *(const float2*)(g_bu_im + idx);
        float nar = fmaf(lA.x, ar, fmaf(-lA.y, ai, ur.x));
        float nai = fmaf(lA.x, ai, fmaf( lA.y, ar, ui.x));
        float nbr = fmaf(lB.x, br, fmaf(-lB.y, bi, ur.y));
        float nbi = fmaf(lB.x, bi, fmaf( lB.y, br, ui.y));
        ar = nar; ai = nai; br = nbr; bi = nbi;
    }
    g_carry[c * DH + h0]     = make_float2(ar, ai);
    g_carry[c * DH + h0 + 1] = make_float2(br, bi);
}

// ---------------- scan phase B ---------------------------------------------
__global__ void __launch_bounds__(256) k_scan_chunks(const float* __restrict__ lamb) {
    const int h = blockIdx.x * 256 + threadIdx.x;
    float2 lam = lambda_of(lamb, h);
    float2 lt = lam;
    #pragma unroll
    for (int i = 0; i < 6; i++) {
        float nr = lt.x * lt.x - lt.y * lt.y;
        float ni = 2.f * lt.x * lt.y;
        lt.x = nr; lt.y = ni;
    }
    float pr = 0.f, pi = 0.f;
    #pragma unroll 4
    for (int c = 0; c < N_CHUNK; c++) {
        g_prefix[c * DH + h] = make_float2(pr, pi);
        float2 e = g_carry[c * DH + h];
        float nr = fmaf(lt.x, pr, fmaf(-lt.y, pi, e.x));
        float ni = fmaf(lt.x, pi, fmaf( lt.y, pr, e.y));
        pr = nr; pi = ni;
    }
}

// ---------------- scan phase C: apply + emit bf16 hi/lo (R8) ---------------
__global__ void __launch_bounds__(256) k_apply(const float* __restrict__ lamb) {
    const int hp = blockIdx.x * 256 + threadIdx.x;
    const int c  = blockIdx.y;
    const int h0 = hp * 2;
    const float2 lA = lambda_of(lamb, h0);
    const float2 lB = lambda_of(lamb, h0 + 1);
    const float2 PA = g_prefix[c * DH + h0];
    const float2 PB = g_prefix[c * DH + h0 + 1];

    float ar = PA.x, ai = PA.y, br = PB.x, bi = PB.y;
    long base = (long)c * T_CHUNK * DH + h0;
    #pragma unroll 4
    for (int t = 0; t < T_CHUNK; t++) {
        long idx = base + (long)t * DH;
        float2 ur = *(const float2*)(g_bu_re + idx);
        float2 ui = *(const float2*)(g_bu_im + idx);
        float nar = fmaf(lA.x, ar, fmaf(-lA.y, ai, ur.x));
        float nai = fmaf(lA.x, ai, fmaf( lA.y, ar, ui.x));
        float nbr = fmaf(lB.x, br, fmaf(-lB.y, bi, ur.y));
        float nbi = fmaf(lB.x, bi, fmaf( lB.y, br, ui.y));
        ar = nar; ai = nai; br = nbr; bi = nbi;

        long m  = (long)c * T_CHUNK + t;
        long ob = m * (2 * DH) + h0;
        __nv_bfloat16 hr0 = __float2bfloat16(ar), hr1 = __float2bfloat16(br);
        __nv_bfloat16 hi0 = __float2bfloat16(ai), hi1 = __float2bfloat16(bi);
        __nv_bfloat162 t2;
        t2.x = hr0; t2.y = hr1; *(__nv_bfloat162*)(g_hh + ob) = t2;
        t2.x = hi0; t2.y = hi1; *(__nv_bfloat162*)(g_hh + ob + DH) = t2;
        t2.x = __float2bfloat16(ar - __bfloat162float(hr0));
        t2.y = __float2bfloat16(br - __bfloat162float(hr1));
        *(__nv_bfloat162*)(g_hl + ob) = t2;
        t2.x = __float2bfloat16(ai - __bfloat162float(hi0));
        t2.y = __float2bfloat16(bi - __bfloat162float(hi1));
        *(__nv_bfloat162*)(g_hl + ob + DH) = t2;
    }
}

// ---------------------------------------------------------------------------
extern "C" void kernel_launch(void* const* d_in, const int* in_sizes, int n_in,
                              void* d_out, int out_size)
{
    const float* X     = (const float*)d_in[0];
    const float* lamb  = (const float*)d_in[1];
    const float* gamma = (const float*)d_in[2];
    const float* Bre   = (const float*)d_in[3];
    const float* Bim   = (const float*)d_in[4];
    const float* Cre   = (const float*)d_in[5];
    const float* Cim   = (const float*)d_in[6];
    const float* Dm    = (const float*)d_in[7];
    float*       Y     = (float*)d_out;

    const int SMEM1 = 2 * S1_SZ;  // 48 KB
    const int SMEM2 = 2 * ST_SZ;  // 64 KB
    cudaFuncSetAttribute(k_gemm1, cudaFuncAttributeMaxDynamicSharedMemorySize, SMEM1);
    cudaFuncSetAttribute(k_gemm2, cudaFuncAttributeMaxDynamicSharedMemorySize, SMEM2);

    k_cvt_x <<<(L_SEQ * DIN / 4) / 256, 256>>>(X);
    k_cvt_b1<<<(2 * DH * DIN / 4) / 256, 256>>>(Bre, Bim, gamma);
    k_cvt_c2<<<(DOUT * K2 / 4) / 256, 256>>>(Cre, Cim, Dm);

    k_gemm1<<<dim3(2 * DH / 64, L_SEQ / 128), 256, SMEM1>>>();

    k_carry      <<<dim3(2, N_CHUNK), 256>>>(lamb);
    k_scan_chunks<<<DH / 256, 256>>>(lamb);
    k_apply      <<<dim3(2, N_CHUNK), 256>>>(lamb);

    k_gemm2<<<dim3(DOUT / 128, L_SEQ / 128), 256, SMEM2>>>(Y);
}

// round 14
// speedup vs baseline: 1.3146x; 1.3013x over previous
#include <cuda_runtime.h>
#include <cuda_fp16.h>
#include <cstdint>

#define L_SEQ   16384
#define DIN     512
#define DH      1024
#define DOUT    512
#define T_CHUNK 64
#define N_CHUNK (L_SEQ / T_CHUNK)   // 256
#define K2      2560                 // concat K for GEMM2

// ---------------- scratch (device globals; runtime alloc forbidden) --------
__device__ __align__(128) float  g_bu_re[L_SEQ * DH];
__device__ __align__(128) float  g_bu_im[L_SEQ * DH];
__device__ __align__(128) float2 g_carry [N_CHUNK * DH];
__device__ __align__(128) float2 g_prefix[N_CHUNK * DH];

__device__ __align__(128) __half g_xh [L_SEQ * DIN];    // X hi
__device__ __align__(128) __half g_xl [L_SEQ * DIN];    // X lo
__device__ __align__(128) __half g_b1 [2 * DH * DIN];   // e^g*[Bre;Bim] (single)
__device__ __align__(128) __half g_hh [L_SEQ * 2 * DH]; // h=[re|im] hi
__device__ __align__(128) __half g_hl [L_SEQ * 2 * DH]; // lo
__device__ __align__(128) __half g_c2 [DOUT * K2];      // [Cre|-Cim|D] (single)

// ---------------- helpers --------------------------------------------------
__device__ __forceinline__ uint32_t smem_u32(const void* p) {
    uint32_t a;
    asm("{ .reg .u64 t; cvta.to.shared.u64 t, %1; cvt.u32.u64 %0, t; }"
        : "=r"(a) : "l"(p));
    return a;
}
__device__ __forceinline__ void cpa16(uint32_t dst, const void* src) {
    asm volatile("cp.async.cg.shared.global [%0], [%1], 16;"
                 :: "r"(dst), "l"(src) : "memory");
}
__device__ __forceinline__ void ldsm4(uint32_t& r0, uint32_t& r1, uint32_t& r2,
                                      uint32_t& r3, uint32_t a) {
    asm volatile("ldmatrix.sync.aligned.m8n8.x4.shared.b16 {%0,%1,%2,%3}, [%4];"
                 : "=r"(r0), "=r"(r1), "=r"(r2), "=r"(r3) : "r"(a));
}
__device__ __forceinline__ void mma16816(float& c0, float& c1, float& c2, float& c3,
                                         uint32_t a0, uint32_t a1, uint32_t a2,
                                         uint32_t a3, uint32_t b0, uint32_t b1) {
    asm volatile(
        "mma.sync.aligned.m16n8k16.row.col.f32.f16.f16.f32 "
        "{%0,%1,%2,%3}, {%4,%5,%6,%7}, {%8,%9}, {%0,%1,%2,%3};"
        : "+f"(c0), "+f"(c1), "+f"(c2), "+f"(c3)
        : "r"(a0), "r"(a1), "r"(a2), "r"(a3), "r"(b0), "r"(b1));
}

__device__ __forceinline__ float2 lambda_of(const float* __restrict__ lamb, int h) {
    float mag = expf(-expf(lamb[h]));
    float th  = expf(lamb[DH + h]);
    float s, c;
    sincosf(th, &s, &c);
    return make_float2(mag * c, mag * s);
}

// split fp32x4 -> fp16 hi + fp16 lo planes
__device__ __forceinline__ void split4h(float4 v, __half* ph, __half* pl) {
    float f[4] = {v.x, v.y, v.z, v.w};
    #pragma unroll
    for (int i = 0; i < 4; i += 2) {
        __half h0 = __float2half_rn(f[i]);
        __half h1 = __float2half_rn(f[i + 1]);
        __half2 h2, l2;
        h2.x = h0; h2.y = h1;
        l2.x = __float2half_rn(f[i] - __half2float(h0));
        l2.y = __float2half_rn(f[i + 1] - __half2float(h1));
        *(__half2*)(ph + i) = h2;
        *(__half2*)(pl + i) = l2;
    }
}
__device__ __forceinline__ void cvt4h(float4 v, __half* p) {
    __half2 a, b;
    a.x = __float2half_rn(v.x); a.y = __float2half_rn(v.y);
    b.x = __float2half_rn(v.z); b.y = __float2half_rn(v.w);
    *(__half2*)(p)     = a;
    *(__half2*)(p + 2) = b;
}

// ---------------- conversion kernels ---------------------------------------
__global__ void __launch_bounds__(256) k_cvt_x(const float* __restrict__ X) {
    int i = blockIdx.x * 256 + threadIdx.x;
    float4 v = ((const float4*)X)[i];
    split4h(v, g_xh + 4 * (long)i, g_xl + 4 * (long)i);
}

__global__ void __launch_bounds__(256) k_cvt_b1(const float* __restrict__ Bre,
                                                const float* __restrict__ Bim,
                                                const float* __restrict__ gamma) {
    int i = blockIdx.x * 256 + threadIdx.x;
    int n  = i / (DIN / 4);
    int kq = (i % (DIN / 4)) * 4;
    float eg = expf(gamma[n & (DH - 1)]);
    const float* src = (n < DH) ? (Bre + (long)n * DIN) : (Bim + (long)(n - DH) * DIN);
    float4 v = *(const float4*)(src + kq);
    v.x *= eg; v.y *= eg; v.z *= eg; v.w *= eg;
    cvt4h(v, g_b1 + (long)n * DIN + kq);
}

__global__ void __launch_bounds__(256) k_cvt_c2(const float* __restrict__ Cre,
                                                const float* __restrict__ Cim,
                                                const float* __restrict__ Dm) {
    int i = blockIdx.x * 256 + threadIdx.x;
    int n  = i / (K2 / 4);
    int kq = (i % (K2 / 4)) * 4;
    float4 v;
    if (kq < 1024) {
        v = *(const float4*)(Cre + (long)n * DH + kq);
    } else if (kq < 2048) {
        v = *(const float4*)(Cim + (long)n * DH + (kq - 1024));
        v.x = -v.x; v.y = -v.y; v.z = -v.z; v.w = -v.w;
    } else {
        v = *(const float4*)(Dm + (long)n * DIN + (kq - 2048));
    }
    cvt4h(v, g_c2 + (long)n * K2 + kq);
}

// ---------------- mma.sync GEMM (2-pass fp16 A-split) ----------------------
// C[128x128 tile] = (Ah+Al) @ B^T.  smem stage: Ah(8K) Al(8K) B(8K) = 24KB,
// double buffered, 2 CTA/SM.
// swizzle: byte = row*64 + ((chunk ^ ((row>>1)&3))*16)
#define ST_A_H 0
#define ST_A_L 8192
#define ST_B   16384
#define ST_SZ  24576

template<int MODE>   // 0: GEMM1 (Bu), 1: GEMM2 (Y)
__global__ void __launch_bounds__(256, 2) k_mma(float* __restrict__ Y) {
    extern __shared__ char sm[];
    const int tid  = threadIdx.x;
    const int lane = tid & 31;
    const int wid  = tid >> 5;
    const int wm   = wid >> 2;          // 0..1 -> 64 rows each
    const int wn   = wid & 3;           // 0..3 -> 32 cols each
    const int m0   = blockIdx.y * 128;
    const int n0   = blockIdx.x * 128;
    const uint32_t smb = smem_u32(sm);
    const int NS = (MODE == 0) ? (DIN / 32) : (K2 / 32);

    float acc[4][4][4];
    #pragma unroll
    for (int a = 0; a < 4; a++)
        #pragma unroll
        for (int b = 0; b < 4; b++)
            #pragma unroll
            for (int c = 0; c < 4; c++) acc[a][b][c] = 0.f;

    const int rloc = lane & 15;
    const int khalf = lane >> 4;
    uint32_t aoff[4], asw[4];
    #pragma unroll
    for (int mf = 0; mf < 4; mf++) {
        int r = wm * 64 + mf * 16 + rloc;
        aoff[mf] = r * 64;
        asw[mf]  = (r >> 1) & 3;
    }
    uint32_t boff[2], bsw[2];
    #pragma unroll
    for (int np = 0; np < 2; np++) {
        int r = wn * 32 + np * 16 + rloc;
        boff[np] = r * 64;
        bsw[np]  = (r >> 1) & 3;
    }

    auto issue_stage = [&](int s, int buf) {
        uint32_t base = smb + buf * ST_SZ;
        int k0 = s * 32;
        const __half *Ah, *Al, *B;
        long lda, ldb; int ka;
        if (MODE == 0) {
            Ah = g_xh; Al = g_xl; lda = DIN; ka = k0;
            B = g_b1; ldb = DIN;
        } else {
            if (k0 < 2 * DH) { Ah = g_hh; Al = g_hl; lda = 2 * DH; ka = k0; }
            else             { Ah = g_xh; Al = g_xl; lda = DIN;    ka = k0 - 2 * DH; }
            B = g_c2; ldb = K2;
        }
        #pragma unroll
        for (int t = 0; t < 2; t++) {
            int idx = tid + t * 256;
            int row = idx >> 2, ch = idx & 3;
            uint32_t doff = row * 64 + ((ch ^ ((row >> 1) & 3)) * 16);
            long ao = (long)(m0 + row) * lda + ka + ch * 8;
            long bo = (long)(n0 + row) * ldb + k0 + ch * 8;
            cpa16(base + ST_A_H + doff, Ah + ao);
            cpa16(base + ST_A_L + doff, Al + ao);
            cpa16(base + ST_B + doff, B + bo);
        }
        asm volatile("cp.async.commit_group;" ::: "memory");
    };

    issue_stage(0, 0);

    for (int s = 0; s < NS; s++) {
        if (s + 1 < NS) {
            issue_stage(s + 1, (s + 1) & 1);
            asm volatile("cp.async.wait_group 1;" ::: "memory");
        } else {
            asm volatile("cp.async.wait_group 0;" ::: "memory");
        }
        __syncthreads();

        uint32_t base = smb + (s & 1) * ST_SZ;
        #pragma unroll
        for (int ks = 0; ks < 2; ks++) {
            const int chunk = ks * 2 + khalf;
            uint32_t ra[4][4], rb[2][4];

            // load A hi + B
            #pragma unroll
            for (int mf = 0; mf < 4; mf++)
                ldsm4(ra[mf][0], ra[mf][1], ra[mf][2], ra[mf][3],
                      base + ST_A_H + aoff[mf] + ((chunk ^ asw[mf]) * 16));
            #pragma unroll
            for (int np = 0; np < 2; np++)
                ldsm4(rb[np][0], rb[np][1], rb[np][2], rb[np][3],
                      base + ST_B + boff[np] + ((chunk ^ bsw[np]) * 16));
            // pass 1: Ah * B
            #pragma unroll
            for (int mf = 0; mf < 4; mf++)
                #pragma unroll
                for (int nf = 0; nf < 4; nf++) {
                    int np = nf >> 1, sel = nf & 1;
                    mma16816(acc[mf][nf][0], acc[mf][nf][1], acc[mf][nf][2], acc[mf][nf][3],
                             ra[mf][0], ra[mf][1], ra[mf][2], ra[mf][3],
                             rb[np][sel], rb[np][sel + 2]);
                }
            // load A lo (overwrite ra); pass 2: Al * B (reuse rb)
            #pragma unroll
            for (int mf = 0; mf < 4; mf++)
                ldsm4(ra[mf][0], ra[mf][1], ra[mf][2], ra[mf][3],
                      base + ST_A_L + aoff[mf] + ((chunk ^ asw[mf]) * 16));
            #pragma unroll
            for (int mf = 0; mf < 4; mf++)
                #pragma unroll
                for (int nf = 0; nf < 4; nf++) {
                    int np = nf >> 1, sel = nf & 1;
                    mma16816(acc[mf][nf][0], acc[mf][nf][1], acc[mf][nf][2], acc[mf][nf][3],
                             ra[mf][0], ra[mf][1], ra[mf][2], ra[mf][3],
                             rb[np][sel], rb[np][sel + 2]);
                }
        }
        __syncthreads();
    }

    // epilogue
    if (MODE == 0) {
        float* plane = (n0 < DH) ? g_bu_re : g_bu_im;
        int nbase = n0 & (DH - 1);
        #pragma unroll
        for (int mf = 0; mf < 4; mf++) {
            int m = m0 + wm * 64 + mf * 16 + (lane >> 2);
            #pragma unroll
            for (int nf = 0; nf < 4; nf++) {
                int nn = nbase + wn * 32 + nf * 8 + (lane & 3) * 2;
                *(float2*)(plane + (long)m * DH + nn) =
                    make_float2(acc[mf][nf][0], acc[mf][nf][1]);
                *(float2*)(plane + (long)(m + 8) * DH + nn) =
                    make_float2(acc[mf][nf][2], acc[mf][nf][3]);
            }
        }
    } else {
        #pragma unroll
        for (int mf = 0; mf < 4; mf++) {
            int m = m0 + wm * 64 + mf * 16 + (lane >> 2);
            #pragma unroll
            for (int nf = 0; nf < 4; nf++) {
                int nn = n0 + wn * 32 + nf * 8 + (lane & 3) * 2;
                *(float2*)(Y + (long)m * DOUT + nn) =
                    make_float2(acc[mf][nf][0], acc[mf][nf][1]);
                *(float2*)(Y + (long)(m + 8) * DOUT + nn) =
                    make_float2(acc[mf][nf][2], acc[mf][nf][3]);
            }
        }
    }
}

// ---------------- scan phase A: chunk carries (2 ch/thread) ----------------
__global__ void __launch_bounds__(256) k_carry(const float* __restrict__ lamb) {
    const int hp = blockIdx.x * 256 + threadIdx.x;
    const int c  = blockIdx.y;
    const int h0 = hp * 2;
    const float2 lA = lambda_of(lamb, h0);
    const float2 lB = lambda_of(lamb, h0 + 1);

    float ar = 0.f, ai = 0.f, br = 0.f, bi = 0.f;
    long base = (long)c * T_CHUNK * DH + h0;
    #pragma unroll 4
    for (int t = 0; t < T_CHUNK; t++) {
        long idx = base + (long)t * DH;
        float2 ur = *(const float2*)(g_bu_re + idx);
        float2 ui = *(const float2*)(g_bu_im + idx);
        float nar = fmaf(lA.x, ar, fmaf(-lA.y, ai, ur.x));
        float nai = fmaf(lA.x, ai, fmaf( lA.y, ar, ui.x));
        float nbr = fmaf(lB.x, br, fmaf(-lB.y, bi, ur.y));
        float nbi = fmaf(lB.x, bi, fmaf( lB.y, br, ui.y));
        ar = nar; ai = nai; br = nbr; bi = nbi;
    }
    g_carry[c * DH + h0]     = make_float2(ar, ai);
    g_carry[c * DH + h0 + 1] = make_float2(br, bi);
}

// ---------------- scan phase B ---------------------------------------------
__global__ void __launch_bounds__(256) k_scan_chunks(const float* __restrict__ lamb) {
    const int h = blockIdx.x * 256 + threadIdx.x;
    float2 lam = lambda_of(lamb, h);
    float2 lt = lam;
    #pragma unroll
    for (int i = 0; i < 6; i++) {
        float nr = lt.x * lt.x - lt.y * lt.y;
        float ni = 2.f * lt.x * lt.y;
        lt.x = nr; lt.y = ni;
    }
    float pr = 0.f, pi = 0.f;
    #pragma unroll 4
    for (int c = 0; c < N_CHUNK; c++) {
        g_prefix[c * DH + h] = make_float2(pr, pi);
        float2 e = g_carry[c * DH + h];
        float nr = fmaf(lt.x, pr, fmaf(-lt.y, pi, e.x));
        float ni = fmaf(lt.x, pi, fmaf( lt.y, pr, e.y));
        pr = nr; pi = ni;
    }
}

// ---------------- scan phase C: apply + emit fp16 hi/lo h planes -----------
__global__ void __launch_bounds__(256) k_apply(const float* __restrict__ lamb) {
    const int hp = blockIdx.x * 256 + threadIdx.x;
    const int c  = blockIdx.y;
    const int h0 = hp * 2;
    const float2 lA = lambda_of(lamb, h0);
    const float2 lB = lambda_of(lamb, h0 + 1);
    const float2 PA = g_prefix[c * DH + h0];
    const float2 PB = g_prefix[c * DH + h0 + 1];

    float ar = PA.x, ai = PA.y, br = PB.x, bi = PB.y;
    long base = (long)c * T_CHUNK * DH + h0;
    #pragma unroll 4
    for (int t = 0; t < T_CHUNK; t++) {
        long idx = base + (long)t * DH;
        float2 ur = *(const float2*)(g_bu_re + idx);
        float2 ui = *(const float2*)(g_bu_im + idx);
        float nar = fmaf(lA.x, ar, fmaf(-lA.y, ai, ur.x));
        float nai = fmaf(lA.x, ai, fmaf( lA.y, ar, ui.x));
        float nbr = fmaf(lB.x, br, fmaf(-lB.y, bi, ur.y));
        float nbi = fmaf(lB.x, bi, fmaf( lB.y, br, ui.y));
        ar = nar; ai = nai; br = nbr; bi = nbi;

        long m  = (long)c * T_CHUNK + t;
        long ob = m * (2 * DH) + h0;
        __half hr0 = __float2half_rn(ar), hr1 = __float2half_rn(br);
        __half hi0 = __float2half_rn(ai), hi1 = __float2half_rn(bi);
        __half2 t2;
        t2.x = hr0; t2.y = hr1; *(__half2*)(g_hh + ob) = t2;
        t2.x = hi0; t2.y = hi1; *(__half2*)(g_hh + ob + DH) = t2;
        t2.x = __float2half_rn(ar - __half2float(hr0));
        t2.y = __float2half_rn(br - __half2float(hr1));
        *(__half2*)(g_hl + ob) = t2;
        t2.x = __float2half_rn(ai - __half2float(hi0));
        t2.y = __float2half_rn(bi - __half2float(hi1));
        *(__half2*)(g_hl + ob + DH) = t2;
    }
}

// ---------------------------------------------------------------------------
extern "C" void kernel_launch(void* const* d_in, const int* in_sizes, int n_in,
                              void* d_out, int out_size)
{
    const float* X     = (const float*)d_in[0];
    const float* lamb  = (const float*)d_in[1];
    const float* gamma = (const float*)d_in[2];
    const float* Bre   = (const float*)d_in[3];
    const float* Bim   = (const float*)d_in[4];
    const float* Cre   = (const float*)d_in[5];
    const float* Cim   = (const float*)d_in[6];
    const float* Dm    = (const float*)d_in[7];
    float*       Y     = (float*)d_out;

    const int SMEM = 2 * ST_SZ;   // 48 KB
    cudaFuncSetAttribute(k_mma<0>, cudaFuncAttributeMaxDynamicSharedMemorySize, SMEM);
    cudaFuncSetAttribute(k_mma<1>, cudaFuncAttributeMaxDynamicSharedMemorySize, SMEM);

    k_cvt_x <<<(L_SEQ * DIN / 4) / 256, 256>>>(X);
    k_cvt_b1<<<(2 * DH * DIN / 4) / 256, 256>>>(Bre, Bim, gamma);
    k_cvt_c2<<<(DOUT * K2 / 4) / 256, 256>>>(Cre, Cim, Dm);

    k_mma<0><<<dim3(2 * DH / 128, L_SEQ / 128), 256, SMEM>>>(nullptr);

    k_carry      <<<dim3(2, N_CHUNK), 256>>>(lamb);
    k_scan_chunks<<<DH / 256, 256>>>(lamb);
    k_apply      <<<dim3(2, N_CHUNK), 256>>>(lamb);

    k_mma<1><<<dim3(DOUT / 128, L_SEQ / 128), 256, SMEM>>>(Y);
}

// round 17
// speedup vs baseline: 2.0008x; 1.5220x over previous
#include <cuda_runtime.h>
#include <cuda_fp16.h>
#include <cstdint>

#define L_SEQ   16384
#define DIN     512
#define DH      1024
#define DOUT    512
#define T_CHUNK 64
#define N_CHUNK (L_SEQ / T_CHUNK)   // 256
#define K2      2560                 // concat K for GEMM2

// ---------------- scratch (device globals; runtime alloc forbidden) --------
__device__ __align__(128) float  g_bu_re[L_SEQ * DH];
__device__ __align__(128) float  g_bu_im[L_SEQ * DH];
__device__ __align__(128) float2 g_carry [N_CHUNK * DH];
__device__ __align__(128) float2 g_prefix[N_CHUNK * DH];

__device__ __align__(128) __half g_x  [L_SEQ * DIN];    // X fp16
__device__ __align__(128) __half g_b1 [2 * DH * DIN];   // e^g*[Bre;Bim]
__device__ __align__(128) __half g_h  [L_SEQ * 2 * DH]; // h=[re|im]
__device__ __align__(128) __half g_c2 [DOUT * K2];      // [Cre|-Cim|D]

// ---------------- helpers --------------------------------------------------
__device__ __forceinline__ uint32_t smem_u32(const void* p) {
    uint32_t a;
    asm("{ .reg .u64 t; cvta.to.shared.u64 t, %1; cvt.u32.u64 %0, t; }"
        : "=r"(a) : "l"(p));
    return a;
}
__device__ __forceinline__ void cpa16(uint32_t dst, const void* src) {
    asm volatile("cp.async.cg.shared.global [%0], [%1], 16;"
                 :: "r"(dst), "l"(src) : "memory");
}
__device__ __forceinline__ void ldsm4(uint32_t& r0, uint32_t& r1, uint32_t& r2,
                                      uint32_t& r3, uint32_t a) {
    asm volatile("ldmatrix.sync.aligned.m8n8.x4.shared.b16 {%0,%1,%2,%3}, [%4];"
                 : "=r"(r0), "=r"(r1), "=r"(r2), "=r"(r3) : "r"(a));
}
__device__ __forceinline__ void mma16816(float& c0, float& c1, float& c2, float& c3,
                                         uint32_t a0, uint32_t a1, uint32_t a2,
                                         uint32_t a3, uint32_t b0, uint32_t b1) {
    asm volatile(
        "mma.sync.aligned.m16n8k16.row.col.f32.f16.f16.f32 "
        "{%0,%1,%2,%3}, {%4,%5,%6,%7}, {%8,%9}, {%0,%1,%2,%3};"
        : "+f"(c0), "+f"(c1), "+f"(c2), "+f"(c3)
        : "r"(a0), "r"(a1), "r"(a2), "r"(a3), "r"(b0), "r"(b1));
}

__device__ __forceinline__ float2 lambda_of(const float* __restrict__ lamb, int h) {
    float mag = expf(-expf(lamb[h]));
    float th  = expf(lamb[DH + h]);
    float s, c;
    sincosf(th, &s, &c);
    return make_float2(mag * c, mag * s);
}

__device__ __forceinline__ void cvt4h(float4 v, __half* p) {
    __half2 a, b;
    a.x = __float2half_rn(v.x); a.y = __float2half_rn(v.y);
    b.x = __float2half_rn(v.z); b.y = __float2half_rn(v.w);
    *(__half2*)(p)     = a;
    *(__half2*)(p + 2) = b;
}

// ---------------- conversion kernels ---------------------------------------
__global__ void __launch_bounds__(256) k_cvt_x(const float* __restrict__ X) {
    int i = blockIdx.x * 256 + threadIdx.x;
    float4 v = ((const float4*)X)[i];
    cvt4h(v, g_x + 4 * (long)i);
}

__global__ void __launch_bounds__(256) k_cvt_b1(const float* __restrict__ Bre,
                                                const float* __restrict__ Bim,
                                                const float* __restrict__ gamma) {
    int i = blockIdx.x * 256 + threadIdx.x;
    int n  = i / (DIN / 4);
    int kq = (i % (DIN / 4)) * 4;
    float eg = expf(gamma[n & (DH - 1)]);
    const float* src = (n < DH) ? (Bre + (long)n * DIN) : (Bim + (long)(n - DH) * DIN);
    float4 v = *(const float4*)(src + kq);
    v.x *= eg; v.y *= eg; v.z *= eg; v.w *= eg;
    cvt4h(v, g_b1 + (long)n * DIN + kq);
}

__global__ void __launch_bounds__(256) k_cvt_c2(const float* __restrict__ Cre,
                                                const float* __restrict__ Cim,
                                                const float* __restrict__ Dm) {
    int i = blockIdx.x * 256 + threadIdx.x;
    int n  = i / (K2 / 4);
    int kq = (i % (K2 / 4)) * 4;
    float4 v;
    if (kq < 1024) {
        v = *(const float4*)(Cre + (long)n * DH + kq);
    } else if (kq < 2048) {
        v = *(const float4*)(Cim + (long)n * DH + (kq - 1024));
        v.x = -v.x; v.y = -v.y; v.z = -v.z; v.w = -v.w;
    } else {
        v = *(const float4*)(Dm + (long)n * DIN + (kq - 2048));
    }
    cvt4h(v, g_c2 + (long)n * K2 + kq);
}

// ---------------- mma.sync GEMM (single-pass fp16) -------------------------
// C[128x128 tile] = A @ B^T.  smem stage: A(8K) B(8K) = 16KB, double buffered.
// swizzle: byte = row*64 + ((chunk ^ ((row>>1)&3))*16)
#define ST_A   0
#define ST_B   8192
#define ST_SZ  16384

template<int MODE>   // 0: GEMM1 (Bu), 1: GEMM2 (Y)
__global__ void __launch_bounds__(256, 2) k_mma(float* __restrict__ Y) {
    extern __shared__ char sm[];
    const int tid  = threadIdx.x;
    const int lane = tid & 31;
    const int wid  = tid >> 5;
    const int wm   = wid >> 2;          // 0..1 -> 64 rows each
    const int wn   = wid & 3;           // 0..3 -> 32 cols each
    const int m0   = blockIdx.y * 128;
    const int n0   = blockIdx.x * 128;
    const uint32_t smb = smem_u32(sm);
    const int NS = (MODE == 0) ? (DIN / 32) : (K2 / 32);

    float acc[4][4][4];
    #pragma unroll
    for (int a = 0; a < 4; a++)
        #pragma unroll
        for (int b = 0; b < 4; b++)
            #pragma unroll
            for (int c = 0; c < 4; c++) acc[a][b][c] = 0.f;

    const int rloc = lane & 15;
    const int khalf = lane >> 4;
    uint32_t aoff[4], asw[4];
    #pragma unroll
    for (int mf = 0; mf < 4; mf++) {
        int r = wm * 64 + mf * 16 + rloc;
        aoff[mf] = r * 64;
        asw[mf]  = (r >> 1) & 3;
    }
    uint32_t boff[2], bsw[2];
    #pragma unroll
    for (int np = 0; np < 2; np++) {
        int r = wn * 32 + np * 16 + rloc;
        boff[np] = r * 64;
        bsw[np]  = (r >> 1) & 3;
    }

    auto issue_stage = [&](int s, int buf) {
        uint32_t base = smb + buf * ST_SZ;
        int k0 = s * 32;
        const __half *A, *B;
        long lda, ldb; int ka;
        if (MODE == 0) {
            A = g_x; lda = DIN; ka = k0;
            B = g_b1; ldb = DIN;
        } else {
            if (k0 < 2 * DH) { A = g_h; lda = 2 * DH; ka = k0; }
            else             { A = g_x; lda = DIN;    ka = k0 - 2 * DH; }
            B = g_c2; ldb = K2;
        }
        #pragma unroll
        for (int t = 0; t < 2; t++) {
            int idx = tid + t * 256;
            int row = idx >> 2, ch = idx & 3;
            uint32_t doff = row * 64 + ((ch ^ ((row >> 1) & 3)) * 16);
            long ao = (long)(m0 + row) * lda + ka + ch * 8;
            long bo = (long)(n0 + row) * ldb + k0 + ch * 8;
            cpa16(base + ST_A + doff, A + ao);
            cpa16(base + ST_B + doff, B + bo);
        }
        asm volatile("cp.async.commit_group;" ::: "memory");
    };

    issue_stage(0, 0);

    for (int s = 0; s < NS; s++) {
        if (s + 1 < NS) {
            issue_stage(s + 1, (s + 1) & 1);
            asm volatile("cp.async.wait_group 1;" ::: "memory");
        } else {
            asm volatile("cp.async.wait_group 0;" ::: "memory");
        }
        __syncthreads();

        uint32_t base = smb + (s & 1) * ST_SZ;
        #pragma unroll
        for (int ks = 0; ks < 2; ks++) {
            const int chunk = ks * 2 + khalf;
            uint32_t ra[4][4], rb[2][4];

            #pragma unroll
            for (int mf = 0; mf < 4; mf++)
                ldsm4(ra[mf][0], ra[mf][1], ra[mf][2], ra[mf][3],
                      base + ST_A + aoff[mf] + ((chunk ^ asw[mf]) * 16));
            #pragma unroll
            for (int np = 0; np < 2; np++)
                ldsm4(rb[np][0], rb[np][1], rb[np][2], rb[np][3],
                      base + ST_B + boff[np] + ((chunk ^ bsw[np]) * 16));
            #pragma unroll
            for (int mf = 0; mf < 4; mf++)
                #pragma unroll
                for (int nf = 0; nf < 4; nf++) {
                    int np = nf >> 1, sel = nf & 1;
                    mma16816(acc[mf][nf][0], acc[mf][nf][1], acc[mf][nf][2], acc[mf][nf][3],
                             ra[mf][0], ra[mf][1], ra[mf][2], ra[mf][3],
                             rb[np][sel], rb[np][sel + 2]);
                }
        }
        __syncthreads();
    }

    // epilogue
    if (MODE == 0) {
        float* plane = (n0 < DH) ? g_bu_re : g_bu_im;
        int nbase = n0 & (DH - 1);
        #pragma unroll
        for (int mf = 0; mf < 4; mf++) {
            int m = m0 + wm * 64 + mf * 16 + (lane >> 2);
            #pragma unroll
            for (int nf = 0; nf < 4; nf++) {
                int nn = nbase + wn * 32 + nf * 8 + (lane & 3) * 2;
                *(float2*)(plane + (long)m * DH + nn) =
                    make_float2(acc[mf][nf][0], acc[mf][nf][1]);
                *(float2*)(plane + (long)(m + 8) * DH + nn) =
                    make_float2(acc[mf][nf][2], acc[mf][nf][3]);
            }
        }
    } else {
        #pragma unroll
        for (int mf = 0; mf < 4; mf++) {
            int m = m0 + wm * 64 + mf * 16 + (lane >> 2);
            #pragma unroll
            for (int nf = 0; nf < 4; nf++) {
                int nn = n0 + wn * 32 + nf * 8 + (lane & 3) * 2;
                *(float2*)(Y + (long)m * DOUT + nn) =
                    make_float2(acc[mf][nf][0], acc[mf][nf][1]);
                *(float2*)(Y + (long)(m + 8) * DOUT + nn) =
                    make_float2(acc[mf][nf][2], acc[mf][nf][3]);
            }
        }
    }
}

// ---------------- scan phase A: chunk carries (2 ch/thread) ----------------
__global__ void __launch_bounds__(256) k_carry(const float* __restrict__ lamb) {
    const int hp = blockIdx.x * 256 + threadIdx.x;
    const int c  = blockIdx.y;
    const int h0 = hp * 2;
    const float2 lA = lambda_of(lamb, h0);
    const float2 lB = lambda_of(lamb, h0 + 1);

    float ar = 0.f, ai = 0.f, br = 0.f, bi = 0.f;
    long base = (long)c * T_CHUNK * DH + h0;
    #pragma unroll 4
    for (int t = 0; t < T_CHUNK; t++) {
        long idx = base + (long)t * DH;
        float2 ur = *(const float2*)(g_bu_re + idx);
        float2 ui = *(const float2*)(g_bu_im + idx);
        float nar = fmaf(lA.x, ar, fmaf(-lA.y, ai, ur.x));
        float nai = fmaf(lA.x, ai, fmaf( lA.y, ar, ui.x));
        float nbr = fmaf(lB.x, br, fmaf(-lB.y, bi, ur.y));
        float nbi = fmaf(lB.x, bi, fmaf( lB.y, br, ui.y));
        ar = nar; ai = nai; br = nbr; bi = nbi;
    }
    g_carry[c * DH + h0]     = make_float2(ar, ai);
    g_carry[c * DH + h0 + 1] = make_float2(br, bi);
}

// ---------------- scan phase B ---------------------------------------------
__global__ void __launch_bounds__(256) k_scan_chunks(const float* __restrict__ lamb) {
    const int h = blockIdx.x * 256 + threadIdx.x;
    float2 lam = lambda_of(lamb, h);
    float2 lt = lam;
    #pragma unroll
    for (int i = 0; i < 6; i++) {
        float nr = lt.x * lt.x - lt.y * lt.y;
        float ni = 2.f * lt.x * lt.y;
        lt.x = nr; lt.y = ni;
    }
    float pr = 0.f, pi = 0.f;
    #pragma unroll 4
    for (int c = 0; c < N_CHUNK; c++) {
        g_prefix[c * DH + h] = make_float2(pr, pi);
        float2 e = g_carry[c * DH + h];
        float nr = fmaf(lt.x, pr, fmaf(-lt.y, pi, e.x));
        float ni = fmaf(lt.x, pi, fmaf( lt.y, pr, e.y));
        pr = nr; pi = ni;
    }
}

// ---------------- scan phase C: apply + emit fp16 h planes -----------------
__global__ void __launch_bounds__(256) k_apply(const float* __restrict__ lamb) {
    const int hp = blockIdx.x * 256 + threadIdx.x;
    const int c  = blockIdx.y;
    const int h0 = hp * 2;
    const float2 lA = lambda_of(lamb, h0);
    const float2 lB = lambda_of(lamb, h0 + 1);
    const float2 PA = g_prefix[c * DH + h0];
    const float2 PB = g_prefix[c * DH + h0 + 1];

    float ar = PA.x, ai = PA.y, br = PB.x, bi = PB.y;
    long base = (long)c * T_CHUNK * DH + h0;
    #pragma unroll 4
    for (int t = 0; t < T_CHUNK; t++) {
        long idx = base + (long)t * DH;
        float2 ur = *(const float2*)(g_bu_re + idx);
        float2 ui = *(const float2*)(g_bu_im + idx);
        float nar = fmaf(lA.x, ar, fmaf(-lA.y, ai, ur.x));
        float nai = fmaf(lA.x, ai, fmaf( lA.y, ar, ui.x));
        float nbr = fmaf(lB.x, br, fmaf(-lB.y, bi, ur.y));
        float nbi = fmaf(lB.x, bi, fmaf( lB.y, br, ui.y));
        ar = nar; ai = nai; br = nbr; bi = nbi;

        long m  = (long)c * T_CHUNK + t;
        long ob = m * (2 * DH) + h0;
        __half2 t2;
        t2.x = __float2half_rn(ar); t2.y = __float2half_rn(br);
        *(__half2*)(g_h + ob) = t2;
        t2.x = __float2half_rn(ai); t2.y = __float2half_rn(bi);
        *(__half2*)(g_h + ob + DH) = t2;
    }
}

// ---------------------------------------------------------------------------
extern "C" void kernel_launch(void* const* d_in, const int* in_sizes, int n_in,
                              void* d_out, int out_size)
{
    const float* X     = (const float*)d_in[0];
    const float* lamb  = (const float*)d_in[1];
    const float* gamma = (const float*)d_in[2];
    const float* Bre   = (const float*)d_in[3];
    const float* Bim   = (const float*)d_in[4];
    const float* Cre   = (const float*)d_in[5];
    const float* Cim   = (const float*)d_in[6];
    const float* Dm    = (const float*)d_in[7];
    float*       Y     = (float*)d_out;

    const int SMEM = 2 * ST_SZ;   // 32 KB
    cudaFuncSetAttribute(k_mma<0>, cudaFuncAttributeMaxDynamicSharedMemorySize, SMEM);
    cudaFuncSetAttribute(k_mma<1>, cudaFuncAttributeMaxDynamicSharedMemorySize, SMEM);

    k_cvt_x <<<(L_SEQ * DIN / 4) / 256, 256>>>(X);
    k_cvt_b1<<<(2 * DH * DIN / 4) / 256, 256>>>(Bre, Bim, gamma);
    k_cvt_c2<<<(DOUT * K2 / 4) / 256, 256>>>(Cre, Cim, Dm);

    k_mma<0><<<dim3(2 * DH / 128, L_SEQ / 128), 256, SMEM>>>(nullptr);

    k_carry      <<<dim3(2, N_CHUNK), 256>>>(lamb);
    k_scan_chunks<<<DH / 256, 256>>>(lamb);
    k_apply      <<<dim3(2, N_CHUNK), 256>>>(lamb);

    k_mma<1><<<dim3(DOUT / 128, L_SEQ / 128), 256, SMEM>>>(Y);
}